// round 13
// baseline (speedup 1.0000x reference)
#include <cuda_runtime.h>
#include <cstdint>

typedef unsigned long long u64;

#define B_    256
#define T_    512
#define NPAIR 128

// ---- packed f32x2 helpers -------------------------------------------------
__device__ __forceinline__ void unpk(u64 v, float& a, float& b) {
    asm("mov.b64 {%0, %1}, %2;" : "=f"(a), "=f"(b) : "l"(v));
}
__device__ __forceinline__ u64 ffma2(u64 a, u64 b, u64 c) {
    u64 d; asm("fma.rn.f32x2 %0, %1, %2, %3;" : "=l"(d) : "l"(a), "l"(b), "l"(c)); return d;
}

// ---- fast activations (MUFU ex2+rcp, ~1e-7 err) ---------------------------
#define L2E 1.4426950408889634f
__device__ __forceinline__ float ex2a(float x) {
    float r; asm("ex2.approx.ftz.f32 %0, %1;" : "=f"(r) : "f"(x)); return r;
}
__device__ __forceinline__ float rcpa(float x) {
    float r; asm("rcp.approx.ftz.f32 %0, %1;" : "=f"(r) : "f"(x)); return r;
}
__device__ __forceinline__ float sga(float x) { return rcpa(1.f + ex2a(-L2E * x)); }
__device__ __forceinline__ float tna(float x) {
    return fmaf(-2.f, rcpa(1.f + ex2a(2.f * L2E * x)), 1.f);
}

// ---- ONE fused kernel: a0+a1+a2 (wide) + b0+b1+b2 (scalar), full skew ------
// 128 blocks (one batch pair), 256 threads. Step s computes:
//   a0@t=s, a1@t=s-1, a2@t=s-2           (groups A/B/C, as round 10)
//   pregate_b0 for t=s-3 (group D, warp-per-gate reduce over smem h2)
//   b0 cell @t=s-4, b1 @t=s-5, b2 @t=s-6 (lanes 0..5 of warp 0)
// b2 writes the final output directly. No other kernels, no global scratch.
//
// dynamic smem layout (bytes):
//   [0,      65536)   wT2 = wih_a2  as ulonglong2[16][256] (permuted rows)
//   [65536, 131072)   wT3 = whh_a2  (permuted rows)
//   [131072,135168)   xs  = float[2][512]
//   [135168,138240)   hs  = float[2 phase][3 layer][2 batch][64]
//   [138240,138304)   pbsm  = float[2 parity][8]   (b0 pregates, raw dots)
//   [138304,138320)   hb0sm = float[2 parity][2]
//   [138320,138336)   hb1sm = float[2 parity][2]
//   [138336,138480)   bps   = float[3][12]  (whh[0:4], wih[4:8], bias[8:12])
#define SMEM_FUSE_BYTES 138496

__global__ __launch_bounds__(256, 1) void fuseAll(
    const float* __restrict__ x, float* __restrict__ out,
    const float* __restrict__ wih_a0, const float* __restrict__ whh_a0,
    const float* __restrict__ bih_a0, const float* __restrict__ bhh_a0,
    const float* __restrict__ wih_a1, const float* __restrict__ whh_a1,
    const float* __restrict__ bih_a1, const float* __restrict__ bhh_a1,
    const float* __restrict__ wih_a2, const float* __restrict__ whh_a2,
    const float* __restrict__ bih_a2, const float* __restrict__ bhh_a2,
    const float* __restrict__ wih_b0, const float* __restrict__ whh_b0,
    const float* __restrict__ bih_b0, const float* __restrict__ bhh_b0,
    const float* __restrict__ wih_b1, const float* __restrict__ whh_b1,
    const float* __restrict__ bih_b1, const float* __restrict__ bhh_b1,
    const float* __restrict__ wih_b2, const float* __restrict__ whh_b2,
    const float* __restrict__ bih_b2, const float* __restrict__ bhh_b2)
{
    extern __shared__ __align__(16) char smem[];
    ulonglong2* wT2 = reinterpret_cast<ulonglong2*>(smem);
    ulonglong2* wT3 = reinterpret_cast<ulonglong2*>(smem + 65536);
    float*  xs    = reinterpret_cast<float*>(smem + 131072);   // [2][512]
    float*  hs    = reinterpret_cast<float*>(smem + 135168);   // [2][3][2][64]
    float*  pbsm  = reinterpret_cast<float*>(smem + 138240);   // [2][8]
    float*  hb0sm = reinterpret_cast<float*>(smem + 138304);   // [2][2]
    float*  hb1sm = reinterpret_cast<float*>(smem + 138320);   // [2][2]
    float*  bps   = reinterpret_cast<float*>(smem + 138336);   // [3][12]

    const int tid  = threadIdx.x;
    const int lane = tid & 31, w = tid >> 5;
    const int gt   = lane & 3;                 // 0=i 1=f 2=g 3=o
    const int u    = w * 8 + (lane >> 2);      // unit 0..63
    const int gq   = gt * 64 + u;              // gate row index
    const bool isF = (gt == 1);
    const int pair = blockIdx.x;

    u64 wr0[32], wr1[32], wr2[32];
    {
        const u64* p0 = reinterpret_cast<const u64*>(whh_a0) + (size_t)gq * 32;
        const u64* p1 = reinterpret_cast<const u64*>(wih_a1) + (size_t)gq * 32;
        const u64* p2 = reinterpret_cast<const u64*>(whh_a1) + (size_t)gq * 32;
#pragma unroll
        for (int j = 0; j < 32; ++j) {
            wr0[j] = __ldg(p0 + j);
            wr1[j] = __ldg(p1 + j);
            wr2[j] = __ldg(p2 + j);
        }
    }
    {
        const ulonglong2* p2 = reinterpret_cast<const ulonglong2*>(wih_a2) + (size_t)gq * 16;
        const ulonglong2* p3 = reinterpret_cast<const ulonglong2*>(whh_a2) + (size_t)gq * 16;
#pragma unroll 4
        for (int i = 0; i < 16; ++i) {
            wT2[i * 256 + tid] = __ldg(p2 + i);
            wT3[i * 256 + tid] = __ldg(p3 + i);
        }
    }
#pragma unroll 2
    for (int k = 0; k < 4; ++k) {
        int i = tid + 256 * k, bl = i >> 9, t = i & 511;
        xs[bl * 512 + t] = x[(size_t)(pair * 2 + bl) * T_ + t];
    }
    if (tid < 128) {
#pragma unroll 2
        for (int q = 0; q < 6; ++q) hs[q * 128 + tid] = 0.f;
    }
    // b-layer smem init
    if (tid < 16) { pbsm[tid] = 0.f; }
    if (tid < 4)  { hb0sm[tid] = 0.f; hb1sm[tid] = 0.f; }
    if (tid == 0) {
#pragma unroll
        for (int g = 0; g < 4; ++g) {
            bps[0 * 12 + g]     = __ldg(whh_b0 + g);
            bps[0 * 12 + 4 + g] = 0.f;
            bps[0 * 12 + 8 + g] = __ldg(bih_b0 + g) + __ldg(bhh_b0 + g);
            bps[1 * 12 + g]     = __ldg(whh_b1 + g);
            bps[1 * 12 + 4 + g] = __ldg(wih_b1 + g);
            bps[1 * 12 + 8 + g] = __ldg(bih_b1 + g) + __ldg(bhh_b1 + g);
            bps[2 * 12 + g]     = __ldg(whh_b2 + g);
            bps[2 * 12 + 4 + g] = __ldg(wih_b2 + g);
            bps[2 * 12 + 8 + g] = __ldg(bih_b2 + g) + __ldg(bhh_b2 + g);
        }
    }

    const float bias0 = __ldg(bih_a0 + gq) + __ldg(bhh_a0 + gq);
    const float bias1 = __ldg(bih_a1 + gq) + __ldg(bhh_a1 + gq);
    const float bias2 = __ldg(bih_a2 + gq) + __ldg(bhh_a2 + gq);
    const float wx0   = __ldg(wih_a0 + gq);

    const bool istanh = (gt == 2);
    const float ca = istanh ? 2.f * L2E : -L2E;
    const float aa = istanh ? 1.f : 0.f;
    const float bm = istanh ? -2.f : 1.f;

    float c0a = 0.f, c0b = 0.f, c1a = 0.f, c1b = 0.f, c2a = 0.f, c2b = 0.f;
    float ccell = 0.f, hcell = 0.f;   // b-cell state for lanes 0..5 of warp 0
    int p = 0;
    __syncthreads();

#pragma unroll 1
    for (int s = 0; s < T_ + 6; ++s) {
        const bool L0 = (s < T_);
        const bool L1 = (s >= 1) & (s < T_ + 1);
        const bool L2 = (s >= 2) & (s < T_ + 2);
        const float* hb = hs + p * 384;
        float* hw = hs + (p ^ 1) * 384;

        float v0a = 0.f, v0b = 0.f, p1a = 0.f, p1b = 0.f;
        float h1a = 0.f, h1b = 0.f, p2a = 0.f, p2b = 0.f;
        float h2a = 0.f, h2b = 0.f;

        if (L0 | L1) {
            const ulonglong2* q0p = reinterpret_cast<const ulonglong2*>(hb + 0);
            const ulonglong2* q1p = reinterpret_cast<const ulonglong2*>(hb + 64);
            u64 ax = 0, bx = 0, ix = 0, jx = 0;
#pragma unroll
            for (int i = 0; i < 16; ++i) {
                ulonglong2 q0 = q0p[i], q1 = q1p[i];
                ax = ffma2(wr0[2 * i], q0.x, ax); ax = ffma2(wr0[2 * i + 1], q0.y, ax);
                bx = ffma2(wr0[2 * i], q1.x, bx); bx = ffma2(wr0[2 * i + 1], q1.y, bx);
                ix = ffma2(wr1[2 * i], q0.x, ix); ix = ffma2(wr1[2 * i + 1], q0.y, ix);
                jx = ffma2(wr1[2 * i], q1.x, jx); jx = ffma2(wr1[2 * i + 1], q1.y, jx);
            }
            float e, o;
            unpk(ax, e, o); v0a = e + o;
            unpk(bx, e, o); v0b = e + o;
            unpk(ix, e, o); p1a = e + o;
            unpk(jx, e, o); p1b = e + o;
        }
        if (L1 | L2) {
            const ulonglong2* q0p = reinterpret_cast<const ulonglong2*>(hb + 128);
            const ulonglong2* q1p = reinterpret_cast<const ulonglong2*>(hb + 192);
            u64 ax = 0, bx = 0, ix = 0, jx = 0;
#pragma unroll
            for (int i = 0; i < 16; ++i) {
                ulonglong2 q0 = q0p[i], q1 = q1p[i];
                ulonglong2 wv = wT2[i * 256 + tid];
                ax = ffma2(wr2[2 * i], q0.x, ax); ax = ffma2(wr2[2 * i + 1], q0.y, ax);
                bx = ffma2(wr2[2 * i], q1.x, bx); bx = ffma2(wr2[2 * i + 1], q1.y, bx);
                ix = ffma2(wv.x, q0.x, ix);       ix = ffma2(wv.y, q0.y, ix);
                jx = ffma2(wv.x, q1.x, jx);       jx = ffma2(wv.y, q1.y, jx);
            }
            float e, o;
            unpk(ax, e, o); h1a = e + o;
            unpk(bx, e, o); h1b = e + o;
            unpk(ix, e, o); p2a = e + o;
            unpk(jx, e, o); p2b = e + o;
        }
        if (L2) {
            const ulonglong2* q0p = reinterpret_cast<const ulonglong2*>(hb + 256);
            const ulonglong2* q1p = reinterpret_cast<const ulonglong2*>(hb + 320);
            u64 ax = 0, bx = 0;
#pragma unroll
            for (int i = 0; i < 16; ++i) {
                ulonglong2 q0 = q0p[i], q1 = q1p[i];
                ulonglong2 wv = wT3[i * 256 + tid];
                ax = ffma2(wv.x, q0.x, ax); ax = ffma2(wv.y, q0.y, ax);
                bx = ffma2(wv.x, q1.x, bx); bx = ffma2(wv.y, q1.y, bx);
            }
            float e, o;
            unpk(ax, e, o); h2a = e + o;
            unpk(bx, e, o); h2b = e + o;
        }

        // ---- group D: pregate_b0(t=s-3) = W_ih_b0 . h2(s-3), warp-per-gate ----
        if (s >= 3 && s < T_ + 3) {
            const u64* h2p = reinterpret_cast<const u64*>(hb + 256 + (w >> 2) * 64);
            u64 hv = h2p[lane];
            u64 wv = __ldg(reinterpret_cast<const u64*>(wih_b0) + (w & 3) * 32 + lane);
            u64 pr = ffma2(wv, hv, 0ull);
            float e, o; unpk(pr, e, o);
            float part = e + o;
#pragma unroll
            for (int off = 16; off; off >>= 1)
                part += __shfl_xor_sync(0xffffffffu, part, off);
            if (lane == 0) pbsm[(s & 1) * 8 + (w >> 2) * 4 + (w & 3)] = part;
        }

        // ---- b-cells: lanes 0..5 of warp 0, one (batch, layer) each ----
        if (tid < 6) {
            const int nb = tid & 1, L = tid >> 1;
            const bool act = (L == 0) ? (s >= 4 && s < T_ + 4)
                           : (L == 1) ? (s >= 5 && s < T_ + 5)
                                      : (s >= 6);
            if (act) {
                const float* bp = bps + L * 12;
                float pre0, pre1, pre2, pre3;
                if (L == 0) {
                    const float* pbx = pbsm + ((s - 1) & 1) * 8 + nb * 4;
                    pre0 = pbx[0] + bp[8]; pre1 = pbx[1] + bp[9];
                    pre2 = pbx[2] + bp[10]; pre3 = pbx[3] + bp[11];
                } else {
                    float hin = (L == 1) ? hb0sm[((s - 1) & 1) * 2 + nb]
                                         : hb1sm[((s - 1) & 1) * 2 + nb];
                    pre0 = fmaf(bp[4], hin, bp[8]);
                    pre1 = fmaf(bp[5], hin, bp[9]);
                    pre2 = fmaf(bp[6], hin, bp[10]);
                    pre3 = fmaf(bp[7], hin, bp[11]);
                }
                float iv = sga(fmaf(bp[0], hcell, pre0));
                float fv = sga(fmaf(bp[1], hcell, pre1));
                float gv = tna(fmaf(bp[2], hcell, pre2));
                float ov = sga(fmaf(bp[3], hcell, pre3));
                ccell = fmaf(fv, ccell, iv * gv);
                hcell = ov * tna(ccell);
                if (L == 0)      hb0sm[(s & 1) * 2 + nb] = hcell;
                else if (L == 1) hb1sm[(s & 1) * 2 + nb] = hcell;
                else             out[(size_t)(pair * 2 + nb) * T_ + (s - 6)] = hcell;
            }
        }

        // ---- a-layer cell updates (quad-gate, in-warp) ----
        if (L0) {
            float va = v0a + fmaf(wx0, xs[s], bias0);
            float vb = v0b + fmaf(wx0, xs[512 + s], bias0);
            float ra = fmaf(bm, rcpa(1.f + ex2a(ca * va)), aa);
            float rb = fmaf(bm, rcpa(1.f + ex2a(ca * vb)), aa);
            float r2a = __shfl_xor_sync(0xffffffffu, ra, 2);
            float r2b = __shfl_xor_sync(0xffffffffu, rb, 2);
            float r1a = __shfl_xor_sync(0xffffffffu, ra * r2a, 1);
            float r1b = __shfl_xor_sync(0xffffffffu, rb * r2b, 1);
            if (isF) {
                c0a = fmaf(ra, c0a, r1a);
                c0b = fmaf(rb, c0b, r1b);
                hw[u]      = r2a * tna(c0a);
                hw[64 + u] = r2b * tna(c0b);
            }
        }
        if (L1) {
            float va = h1a + p1a + bias1;
            float vb = h1b + p1b + bias1;
            float ra = fmaf(bm, rcpa(1.f + ex2a(ca * va)), aa);
            float rb = fmaf(bm, rcpa(1.f + ex2a(ca * vb)), aa);
            float r2a = __shfl_xor_sync(0xffffffffu, ra, 2);
            float r2b = __shfl_xor_sync(0xffffffffu, rb, 2);
            float r1a = __shfl_xor_sync(0xffffffffu, ra * r2a, 1);
            float r1b = __shfl_xor_sync(0xffffffffu, rb * r2b, 1);
            if (isF) {
                c1a = fmaf(ra, c1a, r1a);
                c1b = fmaf(rb, c1b, r1b);
                hw[128 + u] = r2a * tna(c1a);
                hw[192 + u] = r2b * tna(c1b);
            }
        }
        if (L2) {
            float va = h2a + p2a + bias2;
            float vb = h2b + p2b + bias2;
            float ra = fmaf(bm, rcpa(1.f + ex2a(ca * va)), aa);
            float rb = fmaf(bm, rcpa(1.f + ex2a(ca * vb)), aa);
            float r2a = __shfl_xor_sync(0xffffffffu, ra, 2);
            float r2b = __shfl_xor_sync(0xffffffffu, rb, 2);
            float r1a = __shfl_xor_sync(0xffffffffu, ra * r2a, 1);
            float r1b = __shfl_xor_sync(0xffffffffu, rb * r2b, 1);
            if (isF) {
                c2a = fmaf(ra, c2a, r1a);
                c2b = fmaf(rb, c2b, r1b);
                hw[256 + u] = r2a * tna(c2a);
                hw[320 + u] = r2b * tna(c2b);
            }
        }
        __syncthreads();
        p ^= 1;
    }
}

// ---------------------------------------------------------------------------
extern "C" void kernel_launch(void* const* d_in, const int* in_sizes, int n_in,
                              void* d_out, int out_size)
{
    const float* x = (const float*)d_in[0];
    const float *wih_a0 = (const float*)d_in[1],  *whh_a0 = (const float*)d_in[2];
    const float *bih_a0 = (const float*)d_in[3],  *bhh_a0 = (const float*)d_in[4];
    const float *wih_a1 = (const float*)d_in[5],  *whh_a1 = (const float*)d_in[6];
    const float *bih_a1 = (const float*)d_in[7],  *bhh_a1 = (const float*)d_in[8];
    const float *wih_a2 = (const float*)d_in[9],  *whh_a2 = (const float*)d_in[10];
    const float *bih_a2 = (const float*)d_in[11], *bhh_a2 = (const float*)d_in[12];
    const float *wih_b0 = (const float*)d_in[13], *whh_b0 = (const float*)d_in[14];
    const float *bih_b0 = (const float*)d_in[15], *bhh_b0 = (const float*)d_in[16];
    const float *wih_b1 = (const float*)d_in[17], *whh_b1 = (const float*)d_in[18];
    const float *bih_b1 = (const float*)d_in[19], *bhh_b1 = (const float*)d_in[20];
    const float *wih_b2 = (const float*)d_in[21], *whh_b2 = (const float*)d_in[22];
    const float *bih_b2 = (const float*)d_in[23], *bhh_b2 = (const float*)d_in[24];
    float* out = (float*)d_out;

    cudaFuncSetAttribute(fuseAll, cudaFuncAttributeMaxDynamicSharedMemorySize,
                         SMEM_FUSE_BYTES);

    fuseAll<<<NPAIR, 256, SMEM_FUSE_BYTES>>>(
        x, out,
        wih_a0, whh_a0, bih_a0, bhh_a0,
        wih_a1, whh_a1, bih_a1, bhh_a1,
        wih_a2, whh_a2, bih_a2, bhh_a2,
        wih_b0, whh_b0, bih_b0, bhh_b0,
        wih_b1, whh_b1, bih_b1, bhh_b1,
        wih_b2, whh_b2, bih_b2, bhh_b2);
}

// round 14
// speedup vs baseline: 1.1068x; 1.1068x over previous
#include <cuda_runtime.h>
#include <cstdint>

typedef unsigned long long u64;

#define B_    256
#define T_    512
#define NPAIR 128
#define NCONS 8
#define GRID_ (NPAIR + NCONS)

// ---- device scratch (no allocations allowed) ------------------------------
__device__ __align__(16) float g_seqA[(size_t)T_ * B_ * 64];   // [t][b][64]
__device__ int g_prog[NPAIR];                                  // per-pair progress

// ---- packed f32x2 helpers -------------------------------------------------
__device__ __forceinline__ void unpk(u64 v, float& a, float& b) {
    asm("mov.b64 {%0, %1}, %2;" : "=f"(a), "=f"(b) : "l"(v));
}
__device__ __forceinline__ u64 ffma2(u64 a, u64 b, u64 c) {
    u64 d; asm("fma.rn.f32x2 %0, %1, %2, %3;" : "=l"(d) : "l"(a), "l"(b), "l"(c)); return d;
}

// ---- fast activations (MUFU ex2+rcp, ~1e-7 err) ---------------------------
#define L2E 1.4426950408889634f
__device__ __forceinline__ float ex2a(float x) {
    float r; asm("ex2.approx.ftz.f32 %0, %1;" : "=f"(r) : "f"(x)); return r;
}
__device__ __forceinline__ float rcpa(float x) {
    float r; asm("rcp.approx.ftz.f32 %0, %1;" : "=f"(r) : "f"(x)); return r;
}
__device__ __forceinline__ float sga(float x) { return rcpa(1.f + ex2a(-L2E * x)); }
__device__ __forceinline__ float tna(float x) {
    return fmaf(-2.f, rcpa(1.f + ex2a(2.f * L2E * x)), 1.f);
}

// ---- reset progress flags (graph-replay safety) ----------------------------
__global__ void resetk() {
    if (threadIdx.x < NPAIR) g_prog[threadIdx.x] = 0;
}

// ---- ONE grid: 128 producer blocks (fused a0+a1+a2) + 8 consumer blocks ----
// Producer inner loop is byte-identical to round-10 fuseA (940us, protected),
// plus an off-path publish: after each step's barrier, tid0 does
// __threadfence + volatile progress store.
// Consumer block k serves batches [32k, 32k+32): spins on progress flags,
// computes pregate_b0 GEMV (128 threads) and the b0/b1/b2 scalar cells
// (32 threads), writing the final output.
#define SMEM_FUSE_BYTES 138240

__global__ __launch_bounds__(256, 1) void fuseAll(
    const float* __restrict__ x, float* __restrict__ out,
    const float* __restrict__ wih_a0, const float* __restrict__ whh_a0,
    const float* __restrict__ bih_a0, const float* __restrict__ bhh_a0,
    const float* __restrict__ wih_a1, const float* __restrict__ whh_a1,
    const float* __restrict__ bih_a1, const float* __restrict__ bhh_a1,
    const float* __restrict__ wih_a2, const float* __restrict__ whh_a2,
    const float* __restrict__ bih_a2, const float* __restrict__ bhh_a2,
    const float* __restrict__ wih_b0, const float* __restrict__ whh_b0,
    const float* __restrict__ bih_b0, const float* __restrict__ bhh_b0,
    const float* __restrict__ wih_b1, const float* __restrict__ whh_b1,
    const float* __restrict__ bih_b1, const float* __restrict__ bhh_b1,
    const float* __restrict__ wih_b2, const float* __restrict__ whh_b2,
    const float* __restrict__ bih_b2, const float* __restrict__ bhh_b2)
{
    extern __shared__ __align__(16) char smem[];
    const int tid = threadIdx.x;

    if (blockIdx.x < NPAIR) {
        // =================== PRODUCER: fused a0+a1+a2 =====================
        ulonglong2* wT2 = reinterpret_cast<ulonglong2*>(smem);
        ulonglong2* wT3 = reinterpret_cast<ulonglong2*>(smem + 65536);
        float*  xs  = reinterpret_cast<float*>(smem + 131072);   // [2][512]
        float*  hs  = reinterpret_cast<float*>(smem + 135168);   // [2][3][2][64]

        const int lane = tid & 31, w = tid >> 5;
        const int gt   = lane & 3;
        const int u    = w * 8 + (lane >> 2);
        const int gq   = gt * 64 + u;
        const bool isF = (gt == 1);
        const int pair = blockIdx.x;

        u64 wr0[32], wr1[32], wr2[32];
        {
            const u64* p0 = reinterpret_cast<const u64*>(whh_a0) + (size_t)gq * 32;
            const u64* p1 = reinterpret_cast<const u64*>(wih_a1) + (size_t)gq * 32;
            const u64* p2 = reinterpret_cast<const u64*>(whh_a1) + (size_t)gq * 32;
#pragma unroll
            for (int j = 0; j < 32; ++j) {
                wr0[j] = __ldg(p0 + j);
                wr1[j] = __ldg(p1 + j);
                wr2[j] = __ldg(p2 + j);
            }
        }
        {
            const ulonglong2* p2 = reinterpret_cast<const ulonglong2*>(wih_a2) + (size_t)gq * 16;
            const ulonglong2* p3 = reinterpret_cast<const ulonglong2*>(whh_a2) + (size_t)gq * 16;
#pragma unroll 4
            for (int i = 0; i < 16; ++i) {
                wT2[i * 256 + tid] = __ldg(p2 + i);
                wT3[i * 256 + tid] = __ldg(p3 + i);
            }
        }
#pragma unroll 2
        for (int k = 0; k < 4; ++k) {
            int i = tid + 256 * k, bl = i >> 9, t = i & 511;
            xs[bl * 512 + t] = x[(size_t)(pair * 2 + bl) * T_ + t];
        }
        if (tid < 128) {
#pragma unroll 2
            for (int q = 0; q < 6; ++q) hs[q * 128 + tid] = 0.f;
        }

        const float bias0 = __ldg(bih_a0 + gq) + __ldg(bhh_a0 + gq);
        const float bias1 = __ldg(bih_a1 + gq) + __ldg(bhh_a1 + gq);
        const float bias2 = __ldg(bih_a2 + gq) + __ldg(bhh_a2 + gq);
        const float wx0   = __ldg(wih_a0 + gq);

        const bool istanh = (gt == 2);
        const float ca = istanh ? 2.f * L2E : -L2E;
        const float aa = istanh ? 1.f : 0.f;
        const float bm = istanh ? -2.f : 1.f;

        float c0a = 0.f, c0b = 0.f, c1a = 0.f, c1b = 0.f, c2a = 0.f, c2b = 0.f;
        int p = 0;
        __syncthreads();

#pragma unroll 1
        for (int s = 0; s < T_ + 2; ++s) {
            const bool L0 = (s < T_);
            const bool L1 = (s >= 1) & (s < T_ + 1);
            const bool L2 = (s >= 2);
            const float* hb = hs + p * 384;
            float* hw = hs + (p ^ 1) * 384;

            float v0a = 0.f, v0b = 0.f, p1a = 0.f, p1b = 0.f;
            float h1a = 0.f, h1b = 0.f, p2a = 0.f, p2b = 0.f;
            float h2a = 0.f, h2b = 0.f;

            if (L0 | L1) {
                const ulonglong2* q0p = reinterpret_cast<const ulonglong2*>(hb + 0);
                const ulonglong2* q1p = reinterpret_cast<const ulonglong2*>(hb + 64);
                u64 ax = 0, bx = 0, ix = 0, jx = 0;
#pragma unroll
                for (int i = 0; i < 16; ++i) {
                    ulonglong2 q0 = q0p[i], q1 = q1p[i];
                    ax = ffma2(wr0[2 * i], q0.x, ax); ax = ffma2(wr0[2 * i + 1], q0.y, ax);
                    bx = ffma2(wr0[2 * i], q1.x, bx); bx = ffma2(wr0[2 * i + 1], q1.y, bx);
                    ix = ffma2(wr1[2 * i], q0.x, ix); ix = ffma2(wr1[2 * i + 1], q0.y, ix);
                    jx = ffma2(wr1[2 * i], q1.x, jx); jx = ffma2(wr1[2 * i + 1], q1.y, jx);
                }
                float e, o;
                unpk(ax, e, o); v0a = e + o;
                unpk(bx, e, o); v0b = e + o;
                unpk(ix, e, o); p1a = e + o;
                unpk(jx, e, o); p1b = e + o;
            }
            if (L1 | L2) {
                const ulonglong2* q0p = reinterpret_cast<const ulonglong2*>(hb + 128);
                const ulonglong2* q1p = reinterpret_cast<const ulonglong2*>(hb + 192);
                u64 ax = 0, bx = 0, ix = 0, jx = 0;
#pragma unroll
                for (int i = 0; i < 16; ++i) {
                    ulonglong2 q0 = q0p[i], q1 = q1p[i];
                    ulonglong2 wv = wT2[i * 256 + tid];
                    ax = ffma2(wr2[2 * i], q0.x, ax); ax = ffma2(wr2[2 * i + 1], q0.y, ax);
                    bx = ffma2(wr2[2 * i], q1.x, bx); bx = ffma2(wr2[2 * i + 1], q1.y, bx);
                    ix = ffma2(wv.x, q0.x, ix);       ix = ffma2(wv.y, q0.y, ix);
                    jx = ffma2(wv.x, q1.x, jx);       jx = ffma2(wv.y, q1.y, jx);
                }
                float e, o;
                unpk(ax, e, o); h1a = e + o;
                unpk(bx, e, o); h1b = e + o;
                unpk(ix, e, o); p2a = e + o;
                unpk(jx, e, o); p2b = e + o;
            }
            if (L2) {
                const ulonglong2* q0p = reinterpret_cast<const ulonglong2*>(hb + 256);
                const ulonglong2* q1p = reinterpret_cast<const ulonglong2*>(hb + 320);
                u64 ax = 0, bx = 0;
#pragma unroll
                for (int i = 0; i < 16; ++i) {
                    ulonglong2 q0 = q0p[i], q1 = q1p[i];
                    ulonglong2 wv = wT3[i * 256 + tid];
                    ax = ffma2(wv.x, q0.x, ax); ax = ffma2(wv.y, q0.y, ax);
                    bx = ffma2(wv.x, q1.x, bx); bx = ffma2(wv.y, q1.y, bx);
                }
                float e, o;
                unpk(ax, e, o); h2a = e + o;
                unpk(bx, e, o); h2b = e + o;
            }

            if (L0) {
                float va = v0a + fmaf(wx0, xs[s], bias0);
                float vb = v0b + fmaf(wx0, xs[512 + s], bias0);
                float ra = fmaf(bm, rcpa(1.f + ex2a(ca * va)), aa);
                float rb = fmaf(bm, rcpa(1.f + ex2a(ca * vb)), aa);
                float r2a = __shfl_xor_sync(0xffffffffu, ra, 2);
                float r2b = __shfl_xor_sync(0xffffffffu, rb, 2);
                float r1a = __shfl_xor_sync(0xffffffffu, ra * r2a, 1);
                float r1b = __shfl_xor_sync(0xffffffffu, rb * r2b, 1);
                if (isF) {
                    c0a = fmaf(ra, c0a, r1a);
                    c0b = fmaf(rb, c0b, r1b);
                    hw[u]      = r2a * tna(c0a);
                    hw[64 + u] = r2b * tna(c0b);
                }
            }
            if (L1) {
                float va = h1a + p1a + bias1;
                float vb = h1b + p1b + bias1;
                float ra = fmaf(bm, rcpa(1.f + ex2a(ca * va)), aa);
                float rb = fmaf(bm, rcpa(1.f + ex2a(ca * vb)), aa);
                float r2a = __shfl_xor_sync(0xffffffffu, ra, 2);
                float r2b = __shfl_xor_sync(0xffffffffu, rb, 2);
                float r1a = __shfl_xor_sync(0xffffffffu, ra * r2a, 1);
                float r1b = __shfl_xor_sync(0xffffffffu, rb * r2b, 1);
                if (isF) {
                    c1a = fmaf(ra, c1a, r1a);
                    c1b = fmaf(rb, c1b, r1b);
                    hw[128 + u] = r2a * tna(c1a);
                    hw[192 + u] = r2b * tna(c1b);
                }
            }
            if (L2) {
                float va = h2a + p2a + bias2;
                float vb = h2b + p2b + bias2;
                float ra = fmaf(bm, rcpa(1.f + ex2a(ca * va)), aa);
                float rb = fmaf(bm, rcpa(1.f + ex2a(ca * vb)), aa);
                float r2a = __shfl_xor_sync(0xffffffffu, ra, 2);
                float r2b = __shfl_xor_sync(0xffffffffu, rb, 2);
                float r1a = __shfl_xor_sync(0xffffffffu, ra * r2a, 1);
                float r1b = __shfl_xor_sync(0xffffffffu, rb * r2b, 1);
                if (isF) {
                    c2a = fmaf(ra, c2a, r1a);
                    c2b = fmaf(rb, c2b, r1b);
                    float ha = r2a * tna(c2a);
                    float hb2 = r2b * tna(c2b);
                    hw[256 + u] = ha;
                    hw[320 + u] = hb2;
                    g_seqA[((size_t)(s - 2) * B_ + pair * 2 + 0) * 64 + u] = ha;
                    g_seqA[((size_t)(s - 2) * B_ + pair * 2 + 1) * 64 + u] = hb2;
                }
            }
            __syncthreads();
            // publish progress: all h2 writes for t=s-2 are visible after the
            // barrier (CTA order) + gpu-scope fence by tid0 (canonical pattern)
            if (tid == 0 && s >= 2) {
                __threadfence();
                *(volatile int*)&g_prog[pair] = s - 1;
            }
            p ^= 1;
        }
    } else {
        // =================== CONSUMER: b0 + b1 + b2 ======================
        u64*   wsm = reinterpret_cast<u64*>(smem);            // [128] wih_b0
        float* pb  = reinterpret_cast<float*>(smem + 1024);   // [2][128]
        float* bps = reinterpret_cast<float*>(smem + 2048);   // [3][12]

        const int k = blockIdx.x - NPAIR;                     // 0..7
        const int batch0 = k * 32;

        if (tid < 128) wsm[tid] = __ldg(reinterpret_cast<const u64*>(wih_b0) + tid);
        if (tid == 0) {
#pragma unroll
            for (int g = 0; g < 4; ++g) {
                bps[0 * 12 + g]     = __ldg(whh_b0 + g);
                bps[0 * 12 + 4 + g] = 0.f;
                bps[0 * 12 + 8 + g] = __ldg(bih_b0 + g) + __ldg(bhh_b0 + g);
                bps[1 * 12 + g]     = __ldg(whh_b1 + g);
                bps[1 * 12 + 4 + g] = __ldg(wih_b1 + g);
                bps[1 * 12 + 8 + g] = __ldg(bih_b1 + g) + __ldg(bhh_b1 + g);
                bps[2 * 12 + g]     = __ldg(whh_b2 + g);
                bps[2 * 12 + 4 + g] = __ldg(wih_b2 + g);
                bps[2 * 12 + 8 + g] = __ldg(bih_b2 + g) + __ldg(bhh_b2 + g);
            }
        }
        __syncthreads();

        // cell state for threads 0..31 (one batch chain each)
        float h0 = 0.f, c0 = 0.f, h1 = 0.f, c1 = 0.f, h2 = 0.f, c2 = 0.f;
        const int mybatch = batch0 + tid;          // for tid<32
        const int gt = tid & 3;
        const int gb = batch0 + (tid >> 2);        // GEMV batch for tid<128
        const int gpair = gb >> 1;

#pragma unroll 1
        for (int t = 0; t < T_; ++t) {
            // gate: wait until h2(t) for my batch is published
            if (tid < 128) {
                while (*(volatile int*)&g_prog[gpair] < t + 1) __nanosleep(64);
                __threadfence();
                // pregate_b0 dot: gate gt of batch gb over h2(t)[64]
                const u64* hp = reinterpret_cast<const u64*>(g_seqA) +
                                ((size_t)t * B_ + gb) * 32;
                const u64* wp = wsm + gt * 32;
                u64 acc = 0;
#pragma unroll 8
                for (int j = 0; j < 32; ++j)
                    acc = ffma2(wp[j], __ldcg(hp + j), acc);
                float e, o; unpk(acc, e, o);
                pb[(t & 1) * 128 + tid] = e + o;
            }
            __syncthreads();

            if (tid < 32) {
                const float* pq = pb + (t & 1) * 128 + tid * 4;
                // b0
                {
                    const float* bp = bps;
                    float iv = sga(fmaf(bp[0], h0, pq[0] + bp[8]));
                    float fv = sga(fmaf(bp[1], h0, pq[1] + bp[9]));
                    float gv = tna(fmaf(bp[2], h0, pq[2] + bp[10]));
                    float ov = sga(fmaf(bp[3], h0, pq[3] + bp[11]));
                    c0 = fmaf(fv, c0, iv * gv);
                    h0 = ov * tna(c0);
                }
                // b1
                {
                    const float* bp = bps + 12;
                    float iv = sga(fmaf(bp[0], h1, fmaf(bp[4], h0, bp[8])));
                    float fv = sga(fmaf(bp[1], h1, fmaf(bp[5], h0, bp[9])));
                    float gv = tna(fmaf(bp[2], h1, fmaf(bp[6], h0, bp[10])));
                    float ov = sga(fmaf(bp[3], h1, fmaf(bp[7], h0, bp[11])));
                    c1 = fmaf(fv, c1, iv * gv);
                    h1 = ov * tna(c1);
                }
                // b2
                {
                    const float* bp = bps + 24;
                    float iv = sga(fmaf(bp[0], h2, fmaf(bp[4], h1, bp[8])));
                    float fv = sga(fmaf(bp[1], h2, fmaf(bp[5], h1, bp[9])));
                    float gv = tna(fmaf(bp[2], h2, fmaf(bp[6], h1, bp[10])));
                    float ov = sga(fmaf(bp[3], h2, fmaf(bp[7], h1, bp[11])));
                    c2 = fmaf(fv, c2, iv * gv);
                    h2 = ov * tna(c2);
                    out[(size_t)mybatch * T_ + t] = h2;
                }
            }
        }
    }
}

// ---------------------------------------------------------------------------
extern "C" void kernel_launch(void* const* d_in, const int* in_sizes, int n_in,
                              void* d_out, int out_size)
{
    const float* x = (const float*)d_in[0];
    const float *wih_a0 = (const float*)d_in[1],  *whh_a0 = (const float*)d_in[2];
    const float *bih_a0 = (const float*)d_in[3],  *bhh_a0 = (const float*)d_in[4];
    const float *wih_a1 = (const float*)d_in[5],  *whh_a1 = (const float*)d_in[6];
    const float *bih_a1 = (const float*)d_in[7],  *bhh_a1 = (const float*)d_in[8];
    const float *wih_a2 = (const float*)d_in[9],  *whh_a2 = (const float*)d_in[10];
    const float *bih_a2 = (const float*)d_in[11], *bhh_a2 = (const float*)d_in[12];
    const float *wih_b0 = (const float*)d_in[13], *whh_b0 = (const float*)d_in[14];
    const float *bih_b0 = (const float*)d_in[15], *bhh_b0 = (const float*)d_in[16];
    const float *wih_b1 = (const float*)d_in[17], *whh_b1 = (const float*)d_in[18];
    const float *bih_b1 = (const float*)d_in[19], *bhh_b1 = (const float*)d_in[20];
    const float *wih_b2 = (const float*)d_in[21], *whh_b2 = (const float*)d_in[22];
    const float *bih_b2 = (const float*)d_in[23], *bhh_b2 = (const float*)d_in[24];
    float* out = (float*)d_out;

    cudaFuncSetAttribute(fuseAll, cudaFuncAttributeMaxDynamicSharedMemorySize,
                         SMEM_FUSE_BYTES);

    resetk<<<1, 128>>>();
    fuseAll<<<GRID_, 256, SMEM_FUSE_BYTES>>>(
        x, out,
        wih_a0, whh_a0, bih_a0, bhh_a0,
        wih_a1, whh_a1, bih_a1, bhh_a1,
        wih_a2, whh_a2, bih_a2, bhh_a2,
        wih_b0, whh_b0, bih_b0, bhh_b0,
        wih_b1, whh_b1, bih_b1, bhh_b1,
        wih_b2, whh_b2, bih_b2, bhh_b2);
}

// round 15
// speedup vs baseline: 1.2882x; 1.1640x over previous
#include <cuda_runtime.h>
#include <cstdint>

typedef unsigned long long u64;

#define B_    256
#define T_    512
#define NPAIR 128
#define NCONS 8
#define GRID_ (NPAIR + NCONS)

// ---- device scratch (no allocations allowed) ------------------------------
__device__ __align__(16) float g_seqA[(size_t)T_ * B_ * 64];   // [t][b][64]
__device__ int g_prog[NPAIR];                                  // per-pair progress

// ---- packed f32x2 helpers -------------------------------------------------
__device__ __forceinline__ void unpk(u64 v, float& a, float& b) {
    asm("mov.b64 {%0, %1}, %2;" : "=f"(a), "=f"(b) : "l"(v));
}
__device__ __forceinline__ u64 ffma2(u64 a, u64 b, u64 c) {
    u64 d; asm("fma.rn.f32x2 %0, %1, %2, %3;" : "=l"(d) : "l"(a), "l"(b), "l"(c)); return d;
}

// ---- fast activations (MUFU ex2+rcp, ~1e-7 err) ---------------------------
#define L2E 1.4426950408889634f
__device__ __forceinline__ float ex2a(float x) {
    float r; asm("ex2.approx.ftz.f32 %0, %1;" : "=f"(r) : "f"(x)); return r;
}
__device__ __forceinline__ float rcpa(float x) {
    float r; asm("rcp.approx.ftz.f32 %0, %1;" : "=f"(r) : "f"(x)); return r;
}
__device__ __forceinline__ float sga(float x) { return rcpa(1.f + ex2a(-L2E * x)); }
__device__ __forceinline__ float tna(float x) {
    return fmaf(-2.f, rcpa(1.f + ex2a(2.f * L2E * x)), 1.f);
}

// ---- reset progress flags (graph-replay safety) ----------------------------
__global__ void resetk() {
    if (threadIdx.x < NPAIR) g_prog[threadIdx.x] = 0;
}

// ---- ONE grid: 128 producer blocks (fused a0+a1+a2) + 8 consumer blocks ----
// Producer inner loop byte-identical to round-10 fuseA. Progress is published
// only every 16 steps (s ≡ 1 mod 16, s ≥ 17; final publish at s=T+1 carries
// prog=T), amortizing the gpu-scope fence ~16x vs round 14.
// Consumer block k serves batches [32k, 32k+32): spins on progress flags,
// computes pregate_b0 GEMV (128 threads) and b0/b1/b2 cells (32 threads).
#define SMEM_FUSE_BYTES 138240

__global__ __launch_bounds__(256, 1) void fuseAll(
    const float* __restrict__ x, float* __restrict__ out,
    const float* __restrict__ wih_a0, const float* __restrict__ whh_a0,
    const float* __restrict__ bih_a0, const float* __restrict__ bhh_a0,
    const float* __restrict__ wih_a1, const float* __restrict__ whh_a1,
    const float* __restrict__ bih_a1, const float* __restrict__ bhh_a1,
    const float* __restrict__ wih_a2, const float* __restrict__ whh_a2,
    const float* __restrict__ bih_a2, const float* __restrict__ bhh_a2,
    const float* __restrict__ wih_b0, const float* __restrict__ whh_b0,
    const float* __restrict__ bih_b0, const float* __restrict__ bhh_b0,
    const float* __restrict__ wih_b1, const float* __restrict__ whh_b1,
    const float* __restrict__ bih_b1, const float* __restrict__ bhh_b1,
    const float* __restrict__ wih_b2, const float* __restrict__ whh_b2,
    const float* __restrict__ bih_b2, const float* __restrict__ bhh_b2)
{
    extern __shared__ __align__(16) char smem[];
    const int tid = threadIdx.x;

    if (blockIdx.x < NPAIR) {
        // =================== PRODUCER: fused a0+a1+a2 =====================
        ulonglong2* wT2 = reinterpret_cast<ulonglong2*>(smem);
        ulonglong2* wT3 = reinterpret_cast<ulonglong2*>(smem + 65536);
        float*  xs  = reinterpret_cast<float*>(smem + 131072);   // [2][512]
        float*  hs  = reinterpret_cast<float*>(smem + 135168);   // [2][3][2][64]

        const int lane = tid & 31, w = tid >> 5;
        const int gt   = lane & 3;
        const int u    = w * 8 + (lane >> 2);
        const int gq   = gt * 64 + u;
        const bool isF = (gt == 1);
        const int pair = blockIdx.x;

        u64 wr0[32], wr1[32], wr2[32];
        {
            const u64* p0 = reinterpret_cast<const u64*>(whh_a0) + (size_t)gq * 32;
            const u64* p1 = reinterpret_cast<const u64*>(wih_a1) + (size_t)gq * 32;
            const u64* p2 = reinterpret_cast<const u64*>(whh_a1) + (size_t)gq * 32;
#pragma unroll
            for (int j = 0; j < 32; ++j) {
                wr0[j] = __ldg(p0 + j);
                wr1[j] = __ldg(p1 + j);
                wr2[j] = __ldg(p2 + j);
            }
        }
        {
            const ulonglong2* p2 = reinterpret_cast<const ulonglong2*>(wih_a2) + (size_t)gq * 16;
            const ulonglong2* p3 = reinterpret_cast<const ulonglong2*>(whh_a2) + (size_t)gq * 16;
#pragma unroll 4
            for (int i = 0; i < 16; ++i) {
                wT2[i * 256 + tid] = __ldg(p2 + i);
                wT3[i * 256 + tid] = __ldg(p3 + i);
            }
        }
#pragma unroll 2
        for (int k = 0; k < 4; ++k) {
            int i = tid + 256 * k, bl = i >> 9, t = i & 511;
            xs[bl * 512 + t] = x[(size_t)(pair * 2 + bl) * T_ + t];
        }
        if (tid < 128) {
#pragma unroll 2
            for (int q = 0; q < 6; ++q) hs[q * 128 + tid] = 0.f;
        }

        const float bias0 = __ldg(bih_a0 + gq) + __ldg(bhh_a0 + gq);
        const float bias1 = __ldg(bih_a1 + gq) + __ldg(bhh_a1 + gq);
        const float bias2 = __ldg(bih_a2 + gq) + __ldg(bhh_a2 + gq);
        const float wx0   = __ldg(wih_a0 + gq);

        const bool istanh = (gt == 2);
        const float ca = istanh ? 2.f * L2E : -L2E;
        const float aa = istanh ? 1.f : 0.f;
        const float bm = istanh ? -2.f : 1.f;

        float c0a = 0.f, c0b = 0.f, c1a = 0.f, c1b = 0.f, c2a = 0.f, c2b = 0.f;
        int p = 0;
        __syncthreads();

#pragma unroll 1
        for (int s = 0; s < T_ + 2; ++s) {
            const bool L0 = (s < T_);
            const bool L1 = (s >= 1) & (s < T_ + 1);
            const bool L2 = (s >= 2);
            const float* hb = hs + p * 384;
            float* hw = hs + (p ^ 1) * 384;

            float v0a = 0.f, v0b = 0.f, p1a = 0.f, p1b = 0.f;
            float h1a = 0.f, h1b = 0.f, p2a = 0.f, p2b = 0.f;
            float h2a = 0.f, h2b = 0.f;

            if (L0 | L1) {
                const ulonglong2* q0p = reinterpret_cast<const ulonglong2*>(hb + 0);
                const ulonglong2* q1p = reinterpret_cast<const ulonglong2*>(hb + 64);
                u64 ax = 0, bx = 0, ix = 0, jx = 0;
#pragma unroll
                for (int i = 0; i < 16; ++i) {
                    ulonglong2 q0 = q0p[i], q1 = q1p[i];
                    ax = ffma2(wr0[2 * i], q0.x, ax); ax = ffma2(wr0[2 * i + 1], q0.y, ax);
                    bx = ffma2(wr0[2 * i], q1.x, bx); bx = ffma2(wr0[2 * i + 1], q1.y, bx);
                    ix = ffma2(wr1[2 * i], q0.x, ix); ix = ffma2(wr1[2 * i + 1], q0.y, ix);
                    jx = ffma2(wr1[2 * i], q1.x, jx); jx = ffma2(wr1[2 * i + 1], q1.y, jx);
                }
                float e, o;
                unpk(ax, e, o); v0a = e + o;
                unpk(bx, e, o); v0b = e + o;
                unpk(ix, e, o); p1a = e + o;
                unpk(jx, e, o); p1b = e + o;
            }
            if (L1 | L2) {
                const ulonglong2* q0p = reinterpret_cast<const ulonglong2*>(hb + 128);
                const ulonglong2* q1p = reinterpret_cast<const ulonglong2*>(hb + 192);
                u64 ax = 0, bx = 0, ix = 0, jx = 0;
#pragma unroll
                for (int i = 0; i < 16; ++i) {
                    ulonglong2 q0 = q0p[i], q1 = q1p[i];
                    ulonglong2 wv = wT2[i * 256 + tid];
                    ax = ffma2(wr2[2 * i], q0.x, ax); ax = ffma2(wr2[2 * i + 1], q0.y, ax);
                    bx = ffma2(wr2[2 * i], q1.x, bx); bx = ffma2(wr2[2 * i + 1], q1.y, bx);
                    ix = ffma2(wv.x, q0.x, ix);       ix = ffma2(wv.y, q0.y, ix);
                    jx = ffma2(wv.x, q1.x, jx);       jx = ffma2(wv.y, q1.y, jx);
                }
                float e, o;
                unpk(ax, e, o); h1a = e + o;
                unpk(bx, e, o); h1b = e + o;
                unpk(ix, e, o); p2a = e + o;
                unpk(jx, e, o); p2b = e + o;
            }
            if (L2) {
                const ulonglong2* q0p = reinterpret_cast<const ulonglong2*>(hb + 256);
                const ulonglong2* q1p = reinterpret_cast<const ulonglong2*>(hb + 320);
                u64 ax = 0, bx = 0;
#pragma unroll
                for (int i = 0; i < 16; ++i) {
                    ulonglong2 q0 = q0p[i], q1 = q1p[i];
                    ulonglong2 wv = wT3[i * 256 + tid];
                    ax = ffma2(wv.x, q0.x, ax); ax = ffma2(wv.y, q0.y, ax);
                    bx = ffma2(wv.x, q1.x, bx); bx = ffma2(wv.y, q1.y, bx);
                }
                float e, o;
                unpk(ax, e, o); h2a = e + o;
                unpk(bx, e, o); h2b = e + o;
            }

            if (L0) {
                float va = v0a + fmaf(wx0, xs[s], bias0);
                float vb = v0b + fmaf(wx0, xs[512 + s], bias0);
                float ra = fmaf(bm, rcpa(1.f + ex2a(ca * va)), aa);
                float rb = fmaf(bm, rcpa(1.f + ex2a(ca * vb)), aa);
                float r2a = __shfl_xor_sync(0xffffffffu, ra, 2);
                float r2b = __shfl_xor_sync(0xffffffffu, rb, 2);
                float r1a = __shfl_xor_sync(0xffffffffu, ra * r2a, 1);
                float r1b = __shfl_xor_sync(0xffffffffu, rb * r2b, 1);
                if (isF) {
                    c0a = fmaf(ra, c0a, r1a);
                    c0b = fmaf(rb, c0b, r1b);
                    hw[u]      = r2a * tna(c0a);
                    hw[64 + u] = r2b * tna(c0b);
                }
            }
            if (L1) {
                float va = h1a + p1a + bias1;
                float vb = h1b + p1b + bias1;
                float ra = fmaf(bm, rcpa(1.f + ex2a(ca * va)), aa);
                float rb = fmaf(bm, rcpa(1.f + ex2a(ca * vb)), aa);
                float r2a = __shfl_xor_sync(0xffffffffu, ra, 2);
                float r2b = __shfl_xor_sync(0xffffffffu, rb, 2);
                float r1a = __shfl_xor_sync(0xffffffffu, ra * r2a, 1);
                float r1b = __shfl_xor_sync(0xffffffffu, rb * r2b, 1);
                if (isF) {
                    c1a = fmaf(ra, c1a, r1a);
                    c1b = fmaf(rb, c1b, r1b);
                    hw[128 + u] = r2a * tna(c1a);
                    hw[192 + u] = r2b * tna(c1b);
                }
            }
            if (L2) {
                float va = h2a + p2a + bias2;
                float vb = h2b + p2b + bias2;
                float ra = fmaf(bm, rcpa(1.f + ex2a(ca * va)), aa);
                float rb = fmaf(bm, rcpa(1.f + ex2a(ca * vb)), aa);
                float r2a = __shfl_xor_sync(0xffffffffu, ra, 2);
                float r2b = __shfl_xor_sync(0xffffffffu, rb, 2);
                float r1a = __shfl_xor_sync(0xffffffffu, ra * r2a, 1);
                float r1b = __shfl_xor_sync(0xffffffffu, rb * r2b, 1);
                if (isF) {
                    c2a = fmaf(ra, c2a, r1a);
                    c2b = fmaf(rb, c2b, r1b);
                    float ha = r2a * tna(c2a);
                    float hb2 = r2b * tna(c2b);
                    hw[256 + u] = ha;
                    hw[320 + u] = hb2;
                    g_seqA[((size_t)(s - 2) * B_ + pair * 2 + 0) * 64 + u] = ha;
                    g_seqA[((size_t)(s - 2) * B_ + pair * 2 + 1) * 64 + u] = hb2;
                }
            }
            __syncthreads();
            // batched publish: every 16 steps (s = 17, 33, ..., 513).
            // prog = s-1 timesteps complete (t = 0 .. s-2). Final s=513 -> 512.
            if (tid == 0 && (s & 15) == 1 && s >= 17) {
                __threadfence();
                *(volatile int*)&g_prog[pair] = s - 1;
            }
            p ^= 1;
        }
    } else {
        // =================== CONSUMER: b0 + b1 + b2 ======================
        u64*   wsm = reinterpret_cast<u64*>(smem);            // [128] wih_b0
        float* pb  = reinterpret_cast<float*>(smem + 1024);   // [2][128]
        float* bps = reinterpret_cast<float*>(smem + 2048);   // [3][12]

        const int k = blockIdx.x - NPAIR;                     // 0..7
        const int batch0 = k * 32;

        if (tid < 128) wsm[tid] = __ldg(reinterpret_cast<const u64*>(wih_b0) + tid);
        if (tid == 0) {
#pragma unroll
            for (int g = 0; g < 4; ++g) {
                bps[0 * 12 + g]     = __ldg(whh_b0 + g);
                bps[0 * 12 + 4 + g] = 0.f;
                bps[0 * 12 + 8 + g] = __ldg(bih_b0 + g) + __ldg(bhh_b0 + g);
                bps[1 * 12 + g]     = __ldg(whh_b1 + g);
                bps[1 * 12 + 4 + g] = __ldg(wih_b1 + g);
                bps[1 * 12 + 8 + g] = __ldg(bih_b1 + g) + __ldg(bhh_b1 + g);
                bps[2 * 12 + g]     = __ldg(whh_b2 + g);
                bps[2 * 12 + 4 + g] = __ldg(wih_b2 + g);
                bps[2 * 12 + 8 + g] = __ldg(bih_b2 + g) + __ldg(bhh_b2 + g);
            }
        }
        __syncthreads();

        // cell state for threads 0..31 (one batch chain each)
        float h0 = 0.f, c0 = 0.f, h1 = 0.f, c1 = 0.f, h2 = 0.f, c2 = 0.f;
        const int mybatch = batch0 + tid;          // for tid<32
        const int gt = tid & 3;
        const int gb = batch0 + (tid >> 2);        // GEMV batch for tid<128
        const int gpair = gb >> 1;

#pragma unroll 1
        for (int t = 0; t < T_; ++t) {
            // gate: wait until h2(t) for my batch is published
            if (tid < 128) {
                if (*(volatile int*)&g_prog[gpair] < t + 1) {
                    while (*(volatile int*)&g_prog[gpair] < t + 1) __nanosleep(128);
                    __threadfence();
                }
                // pregate_b0 dot: gate gt of batch gb over h2(t)[64]
                const u64* hp = reinterpret_cast<const u64*>(g_seqA) +
                                ((size_t)t * B_ + gb) * 32;
                const u64* wp = wsm + gt * 32;
                u64 acc = 0;
#pragma unroll 8
                for (int j = 0; j < 32; ++j)
                    acc = ffma2(wp[j], __ldcg(hp + j), acc);
                float e, o; unpk(acc, e, o);
                pb[(t & 1) * 128 + tid] = e + o;
            }
            __syncthreads();

            if (tid < 32) {
                const float* pq = pb + (t & 1) * 128 + tid * 4;
                // b0
                {
                    const float* bp = bps;
                    float iv = sga(fmaf(bp[0], h0, pq[0] + bp[8]));
                    float fv = sga(fmaf(bp[1], h0, pq[1] + bp[9]));
                    float gv = tna(fmaf(bp[2], h0, pq[2] + bp[10]));
                    float ov = sga(fmaf(bp[3], h0, pq[3] + bp[11]));
                    c0 = fmaf(fv, c0, iv * gv);
                    h0 = ov * tna(c0);
                }
                // b1
                {
                    const float* bp = bps + 12;
                    float iv = sga(fmaf(bp[0], h1, fmaf(bp[4], h0, bp[8])));
                    float fv = sga(fmaf(bp[1], h1, fmaf(bp[5], h0, bp[9])));
                    float gv = tna(fmaf(bp[2], h1, fmaf(bp[6], h0, bp[10])));
                    float ov = sga(fmaf(bp[3], h1, fmaf(bp[7], h0, bp[11])));
                    c1 = fmaf(fv, c1, iv * gv);
                    h1 = ov * tna(c1);
                }
                // b2
                {
                    const float* bp = bps + 24;
                    float iv = sga(fmaf(bp[0], h2, fmaf(bp[4], h1, bp[8])));
                    float fv = sga(fmaf(bp[1], h2, fmaf(bp[5], h1, bp[9])));
                    float gv = tna(fmaf(bp[2], h2, fmaf(bp[6], h1, bp[10])));
                    float ov = sga(fmaf(bp[3], h2, fmaf(bp[7], h1, bp[11])));
                    c2 = fmaf(fv, c2, iv * gv);
                    h2 = ov * tna(c2);
                    out[(size_t)mybatch * T_ + t] = h2;
                }
            }
        }
    }
}

// ---------------------------------------------------------------------------
extern "C" void kernel_launch(void* const* d_in, const int* in_sizes, int n_in,
                              void* d_out, int out_size)
{
    const float* x = (const float*)d_in[0];
    const float *wih_a0 = (const float*)d_in[1],  *whh_a0 = (const float*)d_in[2];
    const float *bih_a0 = (const float*)d_in[3],  *bhh_a0 = (const float*)d_in[4];
    const float *wih_a1 = (const float*)d_in[5],  *whh_a1 = (const float*)d_in[6];
    const float *bih_a1 = (const float*)d_in[7],  *bhh_a1 = (const float*)d_in[8];
    const float *wih_a2 = (const float*)d_in[9],  *whh_a2 = (const float*)d_in[10];
    const float *bih_a2 = (const float*)d_in[11], *bhh_a2 = (const float*)d_in[12];
    const float *wih_b0 = (const float*)d_in[13], *whh_b0 = (const float*)d_in[14];
    const float *bih_b0 = (const float*)d_in[15], *bhh_b0 = (const float*)d_in[16];
    const float *wih_b1 = (const float*)d_in[17], *whh_b1 = (const float*)d_in[18];
    const float *bih_b1 = (const float*)d_in[19], *bhh_b1 = (const float*)d_in[20];
    const float *wih_b2 = (const float*)d_in[21], *whh_b2 = (const float*)d_in[22];
    const float *bih_b2 = (const float*)d_in[23], *bhh_b2 = (const float*)d_in[24];
    float* out = (float*)d_out;

    cudaFuncSetAttribute(fuseAll, cudaFuncAttributeMaxDynamicSharedMemorySize,
                         SMEM_FUSE_BYTES);

    resetk<<<1, 128>>>();
    fuseAll<<<GRID_, 256, SMEM_FUSE_BYTES>>>(
        x, out,
        wih_a0, whh_a0, bih_a0, bhh_a0,
        wih_a1, whh_a1, bih_a1, bhh_a1,
        wih_a2, whh_a2, bih_a2, bhh_a2,
        wih_b0, whh_b0, bih_b0, bhh_b0,
        wih_b1, whh_b1, bih_b1, bhh_b1,
        wih_b2, whh_b2, bih_b2, bhh_b2);
}

// round 16
// speedup vs baseline: 1.3624x; 1.0576x over previous
#include <cuda_runtime.h>
#include <cstdint>

typedef unsigned long long u64;

#define B_    256
#define T_    512
#define NPAIR 128
#define NCONS 8
#define GRID_ (NPAIR + NCONS)

// ---- device scratch (no allocations allowed) ------------------------------
__device__ __align__(16) float g_seqA[(size_t)T_ * B_ * 64];   // [t][b][64]
__device__ int g_prog[NPAIR];                                  // per-pair progress

// ---- packed f32x2 helpers -------------------------------------------------
__device__ __forceinline__ void unpk(u64 v, float& a, float& b) {
    asm("mov.b64 {%0, %1}, %2;" : "=f"(a), "=f"(b) : "l"(v));
}
__device__ __forceinline__ u64 ffma2(u64 a, u64 b, u64 c) {
    u64 d; asm("fma.rn.f32x2 %0, %1, %2, %3;" : "=l"(d) : "l"(a), "l"(b), "l"(c)); return d;
}

// ---- fast activations (MUFU ex2+rcp, ~1e-7 err) ---------------------------
#define L2E 1.4426950408889634f
__device__ __forceinline__ float ex2a(float x) {
    float r; asm("ex2.approx.ftz.f32 %0, %1;" : "=f"(r) : "f"(x)); return r;
}
__device__ __forceinline__ float rcpa(float x) {
    float r; asm("rcp.approx.ftz.f32 %0, %1;" : "=f"(r) : "f"(x)); return r;
}
__device__ __forceinline__ float sga(float x) { return rcpa(1.f + ex2a(-L2E * x)); }
__device__ __forceinline__ float tna(float x) {
    return fmaf(-2.f, rcpa(1.f + ex2a(2.f * L2E * x)), 1.f);
}

// ---- reset progress flags (graph-replay safety) ----------------------------
__global__ void resetk() {
    if (threadIdx.x < NPAIR) g_prog[threadIdx.x] = 0;
}

// ---- ONE grid: 128 producer blocks (fused a0+a1+a2) + 8 consumer blocks ----
// Producer: boundary steps use the guarded body; the 510 steady steps use a
// guard-free body with all three dot groups hand-merged into one 16-iter
// loop (8 LDS + 20 FFMA2 per iter) for 3x LDS MLP.
// Publish every 8 steps; final publish after the epilogue.
#define SMEM_FUSE_BYTES 138240

__global__ __launch_bounds__(256, 1) void fuseAll(
    const float* __restrict__ x, float* __restrict__ out,
    const float* __restrict__ wih_a0, const float* __restrict__ whh_a0,
    const float* __restrict__ bih_a0, const float* __restrict__ bhh_a0,
    const float* __restrict__ wih_a1, const float* __restrict__ whh_a1,
    const float* __restrict__ bih_a1, const float* __restrict__ bhh_a1,
    const float* __restrict__ wih_a2, const float* __restrict__ whh_a2,
    const float* __restrict__ bih_a2, const float* __restrict__ bhh_a2,
    const float* __restrict__ wih_b0, const float* __restrict__ whh_b0,
    const float* __restrict__ bih_b0, const float* __restrict__ bhh_b0,
    const float* __restrict__ wih_b1, const float* __restrict__ whh_b1,
    const float* __restrict__ bih_b1, const float* __restrict__ bhh_b1,
    const float* __restrict__ wih_b2, const float* __restrict__ whh_b2,
    const float* __restrict__ bih_b2, const float* __restrict__ bhh_b2)
{
    extern __shared__ __align__(16) char smem[];
    const int tid = threadIdx.x;

    if (blockIdx.x < NPAIR) {
        // =================== PRODUCER: fused a0+a1+a2 =====================
        ulonglong2* wT2 = reinterpret_cast<ulonglong2*>(smem);
        ulonglong2* wT3 = reinterpret_cast<ulonglong2*>(smem + 65536);
        float*  xs  = reinterpret_cast<float*>(smem + 131072);   // [2][512]
        float*  hs  = reinterpret_cast<float*>(smem + 135168);   // [2][3][2][64]

        const int lane = tid & 31, w = tid >> 5;
        const int gt   = lane & 3;
        const int u    = w * 8 + (lane >> 2);
        const int gq   = gt * 64 + u;
        const bool isF = (gt == 1);
        const int pair = blockIdx.x;

        u64 wr0[32], wr1[32], wr2[32];
        {
            const u64* p0 = reinterpret_cast<const u64*>(whh_a0) + (size_t)gq * 32;
            const u64* p1 = reinterpret_cast<const u64*>(wih_a1) + (size_t)gq * 32;
            const u64* p2 = reinterpret_cast<const u64*>(whh_a1) + (size_t)gq * 32;
#pragma unroll
            for (int j = 0; j < 32; ++j) {
                wr0[j] = __ldg(p0 + j);
                wr1[j] = __ldg(p1 + j);
                wr2[j] = __ldg(p2 + j);
            }
        }
        {
            const ulonglong2* p2 = reinterpret_cast<const ulonglong2*>(wih_a2) + (size_t)gq * 16;
            const ulonglong2* p3 = reinterpret_cast<const ulonglong2*>(whh_a2) + (size_t)gq * 16;
#pragma unroll 4
            for (int i = 0; i < 16; ++i) {
                wT2[i * 256 + tid] = __ldg(p2 + i);
                wT3[i * 256 + tid] = __ldg(p3 + i);
            }
        }
#pragma unroll 2
        for (int k = 0; k < 4; ++k) {
            int i = tid + 256 * k, bl = i >> 9, t = i & 511;
            xs[bl * 512 + t] = x[(size_t)(pair * 2 + bl) * T_ + t];
        }
        if (tid < 128) {
#pragma unroll 2
            for (int q = 0; q < 6; ++q) hs[q * 128 + tid] = 0.f;
        }

        const float bias0 = __ldg(bih_a0 + gq) + __ldg(bhh_a0 + gq);
        const float bias1 = __ldg(bih_a1 + gq) + __ldg(bhh_a1 + gq);
        const float bias2 = __ldg(bih_a2 + gq) + __ldg(bhh_a2 + gq);
        const float wx0   = __ldg(wih_a0 + gq);

        const bool istanh = (gt == 2);
        const float ca = istanh ? 2.f * L2E : -L2E;
        const float aa = istanh ? 1.f : 0.f;
        const float bm = istanh ? -2.f : 1.f;

        float c0a = 0.f, c0b = 0.f, c1a = 0.f, c1b = 0.f, c2a = 0.f, c2b = 0.f;
        int p = 0;
        __syncthreads();

        // ---------- boundary (guarded) body as a statement macro ----------
#define STEP_GUARDED(S, L0c, L1c, L2c)                                         \
        {                                                                      \
            const bool L0 = (L0c), L1 = (L1c), L2 = (L2c);                     \
            const float* hb = hs + p * 384;                                    \
            float* hw = hs + (p ^ 1) * 384;                                    \
            float v0a = 0.f, v0b = 0.f, p1a = 0.f, p1b = 0.f;                  \
            float h1a = 0.f, h1b = 0.f, p2a = 0.f, p2b = 0.f;                  \
            float h2a = 0.f, h2b = 0.f;                                        \
            if (L0 | L1) {                                                     \
                const ulonglong2* q0p = reinterpret_cast<const ulonglong2*>(hb + 0);  \
                const ulonglong2* q1p = reinterpret_cast<const ulonglong2*>(hb + 64); \
                u64 ax = 0, bx = 0, ix = 0, jx = 0;                            \
                _Pragma("unroll")                                              \
                for (int i = 0; i < 16; ++i) {                                 \
                    ulonglong2 q0 = q0p[i], q1 = q1p[i];                       \
                    ax = ffma2(wr0[2*i], q0.x, ax); ax = ffma2(wr0[2*i+1], q0.y, ax); \
                    bx = ffma2(wr0[2*i], q1.x, bx); bx = ffma2(wr0[2*i+1], q1.y, bx); \
                    ix = ffma2(wr1[2*i], q0.x, ix); ix = ffma2(wr1[2*i+1], q0.y, ix); \
                    jx = ffma2(wr1[2*i], q1.x, jx); jx = ffma2(wr1[2*i+1], q1.y, jx); \
                }                                                              \
                float e, o;                                                    \
                unpk(ax, e, o); v0a = e + o;                                   \
                unpk(bx, e, o); v0b = e + o;                                   \
                unpk(ix, e, o); p1a = e + o;                                   \
                unpk(jx, e, o); p1b = e + o;                                   \
            }                                                                  \
            if (L1 | L2) {                                                     \
                const ulonglong2* q0p = reinterpret_cast<const ulonglong2*>(hb + 128); \
                const ulonglong2* q1p = reinterpret_cast<const ulonglong2*>(hb + 192); \
                u64 ax = 0, bx = 0, ix = 0, jx = 0;                            \
                _Pragma("unroll")                                              \
                for (int i = 0; i < 16; ++i) {                                 \
                    ulonglong2 q0 = q0p[i], q1 = q1p[i];                       \
                    ulonglong2 wv = wT2[i * 256 + tid];                        \
                    ax = ffma2(wr2[2*i], q0.x, ax); ax = ffma2(wr2[2*i+1], q0.y, ax); \
                    bx = ffma2(wr2[2*i], q1.x, bx); bx = ffma2(wr2[2*i+1], q1.y, bx); \
                    ix = ffma2(wv.x, q0.x, ix);     ix = ffma2(wv.y, q0.y, ix);       \
                    jx = ffma2(wv.x, q1.x, jx);     jx = ffma2(wv.y, q1.y, jx);       \
                }                                                              \
                float e, o;                                                    \
                unpk(ax, e, o); h1a = e + o;                                   \
                unpk(bx, e, o); h1b = e + o;                                   \
                unpk(ix, e, o); p2a = e + o;                                   \
                unpk(jx, e, o); p2b = e + o;                                   \
            }                                                                  \
            if (L2) {                                                          \
                const ulonglong2* q0p = reinterpret_cast<const ulonglong2*>(hb + 256); \
                const ulonglong2* q1p = reinterpret_cast<const ulonglong2*>(hb + 320); \
                u64 ax = 0, bx = 0;                                            \
                _Pragma("unroll")                                              \
                for (int i = 0; i < 16; ++i) {                                 \
                    ulonglong2 q0 = q0p[i], q1 = q1p[i];                       \
                    ulonglong2 wv = wT3[i * 256 + tid];                        \
                    ax = ffma2(wv.x, q0.x, ax); ax = ffma2(wv.y, q0.y, ax);    \
                    bx = ffma2(wv.x, q1.x, bx); bx = ffma2(wv.y, q1.y, bx);    \
                }                                                              \
                float e, o;                                                    \
                unpk(ax, e, o); h2a = e + o;                                   \
                unpk(bx, e, o); h2b = e + o;                                   \
            }                                                                  \
            if (L0) {                                                          \
                float va = v0a + fmaf(wx0, xs[(S)], bias0);                    \
                float vb = v0b + fmaf(wx0, xs[512 + (S)], bias0);              \
                float ra = fmaf(bm, rcpa(1.f + ex2a(ca * va)), aa);            \
                float rb = fmaf(bm, rcpa(1.f + ex2a(ca * vb)), aa);            \
                float r2a = __shfl_xor_sync(0xffffffffu, ra, 2);               \
                float r2b = __shfl_xor_sync(0xffffffffu, rb, 2);               \
                float r1a = __shfl_xor_sync(0xffffffffu, ra * r2a, 1);         \
                float r1b = __shfl_xor_sync(0xffffffffu, rb * r2b, 1);         \
                if (isF) {                                                     \
                    c0a = fmaf(ra, c0a, r1a);                                  \
                    c0b = fmaf(rb, c0b, r1b);                                  \
                    hw[u]      = r2a * tna(c0a);                               \
                    hw[64 + u] = r2b * tna(c0b);                               \
                }                                                              \
            }                                                                  \
            if (L1) {                                                          \
                float va = h1a + p1a + bias1;                                  \
                float vb = h1b + p1b + bias1;                                  \
                float ra = fmaf(bm, rcpa(1.f + ex2a(ca * va)), aa);            \
                float rb = fmaf(bm, rcpa(1.f + ex2a(ca * vb)), aa);            \
                float r2a = __shfl_xor_sync(0xffffffffu, ra, 2);               \
                float r2b = __shfl_xor_sync(0xffffffffu, rb, 2);               \
                float r1a = __shfl_xor_sync(0xffffffffu, ra * r2a, 1);         \
                float r1b = __shfl_xor_sync(0xffffffffu, rb * r2b, 1);         \
                if (isF) {                                                     \
                    c1a = fmaf(ra, c1a, r1a);                                  \
                    c1b = fmaf(rb, c1b, r1b);                                  \
                    hw[128 + u] = r2a * tna(c1a);                              \
                    hw[192 + u] = r2b * tna(c1b);                              \
                }                                                              \
            }                                                                  \
            if (L2) {                                                          \
                float va = h2a + p2a + bias2;                                  \
                float vb = h2b + p2b + bias2;                                  \
                float ra = fmaf(bm, rcpa(1.f + ex2a(ca * va)), aa);            \
                float rb = fmaf(bm, rcpa(1.f + ex2a(ca * vb)), aa);            \
                float r2a = __shfl_xor_sync(0xffffffffu, ra, 2);               \
                float r2b = __shfl_xor_sync(0xffffffffu, rb, 2);               \
                float r1a = __shfl_xor_sync(0xffffffffu, ra * r2a, 1);         \
                float r1b = __shfl_xor_sync(0xffffffffu, rb * r2b, 1);         \
                if (isF) {                                                     \
                    c2a = fmaf(ra, c2a, r1a);                                  \
                    c2b = fmaf(rb, c2b, r1b);                                  \
                    float ha = r2a * tna(c2a);                                 \
                    float hb2 = r2b * tna(c2b);                                \
                    hw[256 + u] = ha;                                          \
                    hw[320 + u] = hb2;                                         \
                    g_seqA[((size_t)((S) - 2) * B_ + pair * 2 + 0) * 64 + u] = ha;  \
                    g_seqA[((size_t)((S) - 2) * B_ + pair * 2 + 1) * 64 + u] = hb2; \
                }                                                              \
            }                                                                  \
            __syncthreads();                                                   \
            p ^= 1;                                                            \
        }

        // prologue: s = 0, 1
#pragma unroll 1
        for (int s = 0; s < 2; ++s) {
            STEP_GUARDED(s, true, s >= 1, false);
        }

        // steady state: s = 2 .. T-1, guard-free, merged dot loop
#pragma unroll 1
        for (int s = 2; s < T_; ++s) {
            const float* hb = hs + p * 384;
            float* hw = hs + (p ^ 1) * 384;
            const ulonglong2* A0p = reinterpret_cast<const ulonglong2*>(hb + 0);
            const ulonglong2* A1p = reinterpret_cast<const ulonglong2*>(hb + 64);
            const ulonglong2* B0p = reinterpret_cast<const ulonglong2*>(hb + 128);
            const ulonglong2* B1p = reinterpret_cast<const ulonglong2*>(hb + 192);
            const ulonglong2* C0p = reinterpret_cast<const ulonglong2*>(hb + 256);
            const ulonglong2* C1p = reinterpret_cast<const ulonglong2*>(hb + 320);

            u64 ax = 0, bx = 0, ix = 0, jx = 0;
            u64 aB = 0, bB = 0, iB = 0, jB = 0;
            u64 aC = 0, bC = 0;
#pragma unroll
            for (int i = 0; i < 16; ++i) {
                ulonglong2 qa0 = A0p[i], qa1 = A1p[i];
                ulonglong2 qb0 = B0p[i], qb1 = B1p[i];
                ulonglong2 qc0 = C0p[i], qc1 = C1p[i];
                ulonglong2 w2v = wT2[i * 256 + tid];
                ulonglong2 w3v = wT3[i * 256 + tid];
                ax = ffma2(wr0[2*i], qa0.x, ax); ax = ffma2(wr0[2*i+1], qa0.y, ax);
                bx = ffma2(wr0[2*i], qa1.x, bx); bx = ffma2(wr0[2*i+1], qa1.y, bx);
                ix = ffma2(wr1[2*i], qa0.x, ix); ix = ffma2(wr1[2*i+1], qa0.y, ix);
                jx = ffma2(wr1[2*i], qa1.x, jx); jx = ffma2(wr1[2*i+1], qa1.y, jx);
                aB = ffma2(wr2[2*i], qb0.x, aB); aB = ffma2(wr2[2*i+1], qb0.y, aB);
                bB = ffma2(wr2[2*i], qb1.x, bB); bB = ffma2(wr2[2*i+1], qb1.y, bB);
                iB = ffma2(w2v.x, qb0.x, iB);    iB = ffma2(w2v.y, qb0.y, iB);
                jB = ffma2(w2v.x, qb1.x, jB);    jB = ffma2(w2v.y, qb1.y, jB);
                aC = ffma2(w3v.x, qc0.x, aC);    aC = ffma2(w3v.y, qc0.y, aC);
                bC = ffma2(w3v.x, qc1.x, bC);    bC = ffma2(w3v.y, qc1.y, bC);
            }
            float e, o;
            float v0a, v0b, p1a, p1b, h1a, h1b, p2a, p2b, h2a, h2b;
            unpk(ax, e, o); v0a = e + o;
            unpk(bx, e, o); v0b = e + o;
            unpk(ix, e, o); p1a = e + o;
            unpk(jx, e, o); p1b = e + o;
            unpk(aB, e, o); h1a = e + o;
            unpk(bB, e, o); h1b = e + o;
            unpk(iB, e, o); p2a = e + o;
            unpk(jB, e, o); p2b = e + o;
            unpk(aC, e, o); h2a = e + o;
            unpk(bC, e, o); h2b = e + o;

            // a0 cell
            {
                float va = v0a + fmaf(wx0, xs[s], bias0);
                float vb = v0b + fmaf(wx0, xs[512 + s], bias0);
                float ra = fmaf(bm, rcpa(1.f + ex2a(ca * va)), aa);
                float rb = fmaf(bm, rcpa(1.f + ex2a(ca * vb)), aa);
                float r2a = __shfl_xor_sync(0xffffffffu, ra, 2);
                float r2b = __shfl_xor_sync(0xffffffffu, rb, 2);
                float r1a = __shfl_xor_sync(0xffffffffu, ra * r2a, 1);
                float r1b = __shfl_xor_sync(0xffffffffu, rb * r2b, 1);
                if (isF) {
                    c0a = fmaf(ra, c0a, r1a);
                    c0b = fmaf(rb, c0b, r1b);
                    hw[u]      = r2a * tna(c0a);
                    hw[64 + u] = r2b * tna(c0b);
                }
            }
            // a1 cell
            {
                float va = h1a + p1a + bias1;
                float vb = h1b + p1b + bias1;
                float ra = fmaf(bm, rcpa(1.f + ex2a(ca * va)), aa);
                float rb = fmaf(bm, rcpa(1.f + ex2a(ca * vb)), aa);
                float r2a = __shfl_xor_sync(0xffffffffu, ra, 2);
                float r2b = __shfl_xor_sync(0xffffffffu, rb, 2);
                float r1a = __shfl_xor_sync(0xffffffffu, ra * r2a, 1);
                float r1b = __shfl_xor_sync(0xffffffffu, rb * r2b, 1);
                if (isF) {
                    c1a = fmaf(ra, c1a, r1a);
                    c1b = fmaf(rb, c1b, r1b);
                    hw[128 + u] = r2a * tna(c1a);
                    hw[192 + u] = r2b * tna(c1b);
                }
            }
            // a2 cell + seq store
            {
                float va = h2a + p2a + bias2;
                float vb = h2b + p2b + bias2;
                float ra = fmaf(bm, rcpa(1.f + ex2a(ca * va)), aa);
                float rb = fmaf(bm, rcpa(1.f + ex2a(ca * vb)), aa);
                float r2a = __shfl_xor_sync(0xffffffffu, ra, 2);
                float r2b = __shfl_xor_sync(0xffffffffu, rb, 2);
                float r1a = __shfl_xor_sync(0xffffffffu, ra * r2a, 1);
                float r1b = __shfl_xor_sync(0xffffffffu, rb * r2b, 1);
                if (isF) {
                    c2a = fmaf(ra, c2a, r1a);
                    c2b = fmaf(rb, c2b, r1b);
                    float ha = r2a * tna(c2a);
                    float hb2 = r2b * tna(c2b);
                    hw[256 + u] = ha;
                    hw[320 + u] = hb2;
                    g_seqA[((size_t)(s - 2) * B_ + pair * 2 + 0) * 64 + u] = ha;
                    g_seqA[((size_t)(s - 2) * B_ + pair * 2 + 1) * 64 + u] = hb2;
                }
            }
            __syncthreads();
            // batched publish every 8 steps: s = 9, 17, ..., 505 -> prog 8..504
            if (tid == 0 && (s & 7) == 1 && s >= 9) {
                __threadfence();
                *(volatile int*)&g_prog[pair] = s - 1;
            }
            p ^= 1;
        }

        // epilogue: s = T, T+1
#pragma unroll 1
        for (int s = T_; s < T_ + 2; ++s) {
            STEP_GUARDED(s, false, s < T_ + 1, true);
        }
        // final publish: all T timesteps complete
        if (tid == 0) {
            __threadfence();
            *(volatile int*)&g_prog[pair] = T_;
        }
#undef STEP_GUARDED
    } else {
        // =================== CONSUMER: b0 + b1 + b2 ======================
        u64*   wsm = reinterpret_cast<u64*>(smem);            // [128] wih_b0
        float* pb  = reinterpret_cast<float*>(smem + 1024);   // [2][128]
        float* bps = reinterpret_cast<float*>(smem + 2048);   // [3][12]

        const int k = blockIdx.x - NPAIR;                     // 0..7
        const int batch0 = k * 32;

        if (tid < 128) wsm[tid] = __ldg(reinterpret_cast<const u64*>(wih_b0) + tid);
        if (tid == 0) {
#pragma unroll
            for (int g = 0; g < 4; ++g) {
                bps[0 * 12 + g]     = __ldg(whh_b0 + g);
                bps[0 * 12 + 4 + g] = 0.f;
                bps[0 * 12 + 8 + g] = __ldg(bih_b0 + g) + __ldg(bhh_b0 + g);
                bps[1 * 12 + g]     = __ldg(whh_b1 + g);
                bps[1 * 12 + 4 + g] = __ldg(wih_b1 + g);
                bps[1 * 12 + 8 + g] = __ldg(bih_b1 + g) + __ldg(bhh_b1 + g);
                bps[2 * 12 + g]     = __ldg(whh_b2 + g);
                bps[2 * 12 + 4 + g] = __ldg(wih_b2 + g);
                bps[2 * 12 + 8 + g] = __ldg(bih_b2 + g) + __ldg(bhh_b2 + g);
            }
        }
        __syncthreads();

        float h0 = 0.f, c0 = 0.f, h1 = 0.f, c1 = 0.f, h2 = 0.f, c2 = 0.f;
        const int mybatch = batch0 + tid;          // for tid<32
        const int gt = tid & 3;
        const int gb = batch0 + (tid >> 2);        // GEMV batch for tid<128
        const int gpair = gb >> 1;

#pragma unroll 1
        for (int t = 0; t < T_; ++t) {
            if (tid < 128) {
                if (*(volatile int*)&g_prog[gpair] < t + 1) {
                    while (*(volatile int*)&g_prog[gpair] < t + 1) __nanosleep(128);
                    __threadfence();
                }
                const u64* hp = reinterpret_cast<const u64*>(g_seqA) +
                                ((size_t)t * B_ + gb) * 32;
                const u64* wp = wsm + gt * 32;
                u64 acc = 0;
#pragma unroll 8
                for (int j = 0; j < 32; ++j)
                    acc = ffma2(wp[j], __ldcg(hp + j), acc);
                float e, o; unpk(acc, e, o);
                pb[(t & 1) * 128 + tid] = e + o;
            }
            __syncthreads();

            if (tid < 32) {
                const float* pq = pb + (t & 1) * 128 + tid * 4;
                {
                    const float* bp = bps;
                    float iv = sga(fmaf(bp[0], h0, pq[0] + bp[8]));
                    float fv = sga(fmaf(bp[1], h0, pq[1] + bp[9]));
                    float gv = tna(fmaf(bp[2], h0, pq[2] + bp[10]));
                    float ov = sga(fmaf(bp[3], h0, pq[3] + bp[11]));
                    c0 = fmaf(fv, c0, iv * gv);
                    h0 = ov * tna(c0);
                }
                {
                    const float* bp = bps + 12;
                    float iv = sga(fmaf(bp[0], h1, fmaf(bp[4], h0, bp[8])));
                    float fv = sga(fmaf(bp[1], h1, fmaf(bp[5], h0, bp[9])));
                    float gv = tna(fmaf(bp[2], h1, fmaf(bp[6], h0, bp[10])));
                    float ov = sga(fmaf(bp[3], h1, fmaf(bp[7], h0, bp[11])));
                    c1 = fmaf(fv, c1, iv * gv);
                    h1 = ov * tna(c1);
                }
                {
                    const float* bp = bps + 24;
                    float iv = sga(fmaf(bp[0], h2, fmaf(bp[4], h1, bp[8])));
                    float fv = sga(fmaf(bp[1], h2, fmaf(bp[5], h1, bp[9])));
                    float gv = tna(fmaf(bp[2], h2, fmaf(bp[6], h1, bp[10])));
                    float ov = sga(fmaf(bp[3], h2, fmaf(bp[7], h1, bp[11])));
                    c2 = fmaf(fv, c2, iv * gv);
                    h2 = ov * tna(c2);
                    out[(size_t)mybatch * T_ + t] = h2;
                }
            }
        }
    }
}

// ---------------------------------------------------------------------------
extern "C" void kernel_launch(void* const* d_in, const int* in_sizes, int n_in,
                              void* d_out, int out_size)
{
    const float* x = (const float*)d_in[0];
    const float *wih_a0 = (const float*)d_in[1],  *whh_a0 = (const float*)d_in[2];
    const float *bih_a0 = (const float*)d_in[3],  *bhh_a0 = (const float*)d_in[4];
    const float *wih_a1 = (const float*)d_in[5],  *whh_a1 = (const float*)d_in[6];
    const float *bih_a1 = (const float*)d_in[7],  *bhh_a1 = (const float*)d_in[8];
    const float *wih_a2 = (const float*)d_in[9],  *whh_a2 = (const float*)d_in[10];
    const float *bih_a2 = (const float*)d_in[11], *bhh_a2 = (const float*)d_in[12];
    const float *wih_b0 = (const float*)d_in[13], *whh_b0 = (const float*)d_in[14];
    const float *bih_b0 = (const float*)d_in[15], *bhh_b0 = (const float*)d_in[16];
    const float *wih_b1 = (const float*)d_in[17], *whh_b1 = (const float*)d_in[18];
    const float *bih_b1 = (const float*)d_in[19], *bhh_b1 = (const float*)d_in[20];
    const float *wih_b2 = (const float*)d_in[21], *whh_b2 = (const float*)d_in[22];
    const float *bih_b2 = (const float*)d_in[23], *bhh_b2 = (const float*)d_in[24];
    float* out = (float*)d_out;

    cudaFuncSetAttribute(fuseAll, cudaFuncAttributeMaxDynamicSharedMemorySize,
                         SMEM_FUSE_BYTES);

    resetk<<<1, 128>>>();
    fuseAll<<<GRID_, 256, SMEM_FUSE_BYTES>>>(
        x, out,
        wih_a0, whh_a0, bih_a0, bhh_a0,
        wih_a1, whh_a1, bih_a1, bhh_a1,
        wih_a2, whh_a2, bih_a2, bhh_a2,
        wih_b0, whh_b0, bih_b0, bhh_b0,
        wih_b1, whh_b1, bih_b1, bhh_b1,
        wih_b2, whh_b2, bih_b2, bhh_b2);
}